// round 11
// baseline (speedup 1.0000x reference)
#include <cuda_runtime.h>
#include <cuda_fp16.h>

// Problem constants (fixed by dataset)
#define MAXN 50000
#define CDIM 64
#define SDIM 4
#define ODIM 64
#define KNEI 16
#define DEGCAP 128

// Scratch (static __device__ — allocation-free per harness rules)
__device__ __half2 g_vh[MAXN * 128];          // 25.6 MB v-table (fp16)
__device__ float   g_t[MAXN * SDIM];          // x[n]@Wt + bt
__device__ float   g_sl[MAXN * SDIM];         // src[j]@Ws + bs
__device__ int     g_cnt[MAXN];               // inverse-index counts
__device__ int     g_list[MAXN * DEGCAP];     // inverse-index ref lists (25.6 MB)

// W_lin pre-split into mma B-fragment layout (hi/lo fp16 halves).
__device__ __half2 g_Bhi[8192];
__device__ __half2 g_Blo[8192];
__device__ __half2 g_WtHi[256];
__device__ __half2 g_WtLo[256];
__device__ __half2 g_WsHi[256];
__device__ __half2 g_WsLo[256];

// ---------------------------------------------------------------------------
// Prep: split W_lin (+ Wt, Ws) into fp16 hi/lo B-fragments; zero g_cnt.
// ---------------------------------------------------------------------------
__global__ void k_prep(const float* __restrict__ W_lin,
                       const float* __restrict__ Wt,
                       const float* __restrict__ Ws)
{
    if (blockIdx.x >= 34) {      // zeroing role
        int z = (blockIdx.x - 34) * 256 + threadIdx.x;
        if (z < MAXN) g_cnt[z] = 0;
        return;
    }
    int i = blockIdx.x * 256 + threadIdx.x;
    if (i < 8192) {
        int wh  = i & 1;
        int tig = (i >> 1) & 3;
        int col = (i >> 3) & 255;
        int ks  = i >> 11;
        int s = col >> 6, o = col & 63;
        int k = ks * 16 + wh * 8 + 2 * tig;

        float w0 = __ldg(W_lin + s * 4096 + k * 64 + o);
        float w1 = __ldg(W_lin + s * 4096 + (k + 1) * 64 + o);
        __half h0 = __float2half_rn(w0), h1 = __float2half_rn(w1);
        __half l0 = __float2half_rn(w0 - __half2float(h0));
        __half l1 = __float2half_rn(w1 - __half2float(h1));
        g_Bhi[i] = __halves2half2(h0, h1);
        g_Blo[i] = __halves2half2(l0, l1);
    } else if (i < 8704) {
        int idx = i - 8192;
        int mat = idx >> 8;            // 0 = Wt, 1 = Ws
        int e   = idx & 255;
        int wh = e & 1, tig = (e >> 1) & 3, col = (e >> 3) & 7, ks = (e >> 6) & 3;
        int k = ks * 16 + wh * 8 + 2 * tig;
        const float* W = mat ? Ws : Wt;
        float w0 = 0.f, w1 = 0.f;
        if (col < 4) {
            w0 = __ldg(W + k * 4 + col);
            w1 = __ldg(W + (k + 1) * 4 + col);
        }
        __half h0 = __float2half_rn(w0), h1 = __float2half_rn(w1);
        __half l0 = __float2half_rn(w0 - __half2float(h0));
        __half l1 = __float2half_rn(w1 - __half2float(h1));
        if (mat) { g_WsHi[e] = __halves2half2(h0, h1); g_WsLo[e] = __halves2half2(l0, l1); }
        else     { g_WtHi[e] = __halves2half2(h0, h1); g_WtLo[e] = __halves2half2(l0, l1); }
    }
}

__device__ __forceinline__ void mma16816(float& c0, float& c1, float& c2, float& c3,
                                         unsigned a0, unsigned a1, unsigned a2, unsigned a3,
                                         unsigned b0, unsigned b1)
{
    asm volatile("mma.sync.aligned.m16n8k16.row.col.f32.f16.f16.f32 "
                 "{%0,%1,%2,%3}, {%4,%5,%6,%7}, {%8,%9}, {%0,%1,%2,%3};"
                 : "+f"(c0), "+f"(c1), "+f"(c2), "+f"(c3)
                 : "r"(a0), "r"(a1), "r"(a2), "r"(a3), "r"(b0), "r"(b1));
}

// ---------------------------------------------------------------------------
// Fused kernel: role-split grid.
//   blocks [0, tiles)     : v-table GEMM + logits GEMMs (HMMA, as R10)
//   blocks [tiles, ...)   : inverse-index build (atomic scatter of ref ids)
// ---------------------------------------------------------------------------
__global__ void __launch_bounds__(256, 2) k_tables(const float* __restrict__ x,
                                                   const float* __restrict__ src,
                                                   const float* __restrict__ bt,
                                                   const float* __restrict__ bs,
                                                   const float* __restrict__ b_lin,
                                                   const int* __restrict__ idx,
                                                   int N, int NK, int tiles)
{
    if ((int)blockIdx.x >= tiles) {
        // ---------------- inverse-index build role ----------------
        int w = (blockIdx.x - tiles) * 256 + threadIdx.x;
        if (w < NK) {
            int j = __ldg(idx + w);
            int p = atomicAdd(&g_cnt[j], 1);
            if (p < DEGCAP) g_list[j * DEGCAP + p] = w;
        }
        return;
    }

    __shared__ __align__(16) char smraw[33856];
    __half2* AH = reinterpret_cast<__half2*>(smraw);            // src hi [64][33]
    __half2* AL = AH + 2112;                                    // src lo
    __half2* XH = AH + 4224;                                    // x hi
    __half2* XL = AH + 6336;                                    // x lo
    __half2* CS = reinterpret_cast<__half2*>(smraw);            // epilogue reuse [64][132]

    int t    = threadIdx.x;
    int lane = t & 31;
    int wid  = t >> 5;
    int g    = lane >> 2;
    int tig  = lane & 3;
    int wm   = wid & 3;
    int wn   = wid >> 2;
    int m0   = wm * 16;
    int j0   = blockIdx.x * 64;

    // ---- stage src and x tiles as fp16 hi/lo ----
    {
        int row  = t >> 2;
        int quad = t & 3;
        int jg = j0 + row;
        const float4* srp = (const float4*)(src + (size_t)jg * CDIM) + quad * 4;
        const float4* xrp = (const float4*)(x   + (size_t)jg * CDIM) + quad * 4;
#pragma unroll
        for (int ii = 0; ii < 4; ii++) {
            float4 v = (jg < N) ? __ldg(srp + ii) : make_float4(0.f, 0.f, 0.f, 0.f);
            float4 u = (jg < N) ? __ldg(xrp + ii) : make_float4(0.f, 0.f, 0.f, 0.f);
            int cp = quad * 8 + ii * 2;
            {
                __half hx = __float2half_rn(v.x), hy = __float2half_rn(v.y);
                __half hz = __float2half_rn(v.z), hw = __float2half_rn(v.w);
                AH[row * 33 + cp]     = __halves2half2(hx, hy);
                AH[row * 33 + cp + 1] = __halves2half2(hz, hw);
                AL[row * 33 + cp]     = __halves2half2(__float2half_rn(v.x - __half2float(hx)),
                                                       __float2half_rn(v.y - __half2float(hy)));
                AL[row * 33 + cp + 1] = __halves2half2(__float2half_rn(v.z - __half2float(hz)),
                                                       __float2half_rn(v.w - __half2float(hw)));
            }
            {
                __half hx = __float2half_rn(u.x), hy = __float2half_rn(u.y);
                __half hz = __float2half_rn(u.z), hw = __float2half_rn(u.w);
                XH[row * 33 + cp]     = __halves2half2(hx, hy);
                XH[row * 33 + cp + 1] = __halves2half2(hz, hw);
                XL[row * 33 + cp]     = __halves2half2(__float2half_rn(u.x - __half2float(hx)),
                                                       __float2half_rn(u.y - __half2float(hy)));
                XL[row * 33 + cp + 1] = __halves2half2(__float2half_rn(u.z - __half2float(hz)),
                                                       __float2half_rn(u.w - __half2float(hw)));
            }
        }
    }
    __syncthreads();

    const unsigned* AHu = reinterpret_cast<const unsigned*>(AH);
    const unsigned* ALu = reinterpret_cast<const unsigned*>(AL);
    const unsigned* XHu = reinterpret_cast<const unsigned*>(XH);
    const unsigned* XLu = reinterpret_cast<const unsigned*>(XL);
    const uint2* BH = reinterpret_cast<const uint2*>(g_Bhi);
    const uint2* BL = reinterpret_cast<const uint2*>(g_Blo);

    float c[16][4];
#pragma unroll
    for (int nt = 0; nt < 16; nt++)
#pragma unroll
        for (int r = 0; r < 4; r++) c[nt][r] = 0.f;

    unsigned Af[4][4];
#pragma unroll
    for (int ks = 0; ks < 4; ks++) {
        Af[ks][0] = AHu[(m0 + g) * 33 + ks * 8 + tig];
        Af[ks][1] = AHu[(m0 + g + 8) * 33 + ks * 8 + tig];
        Af[ks][2] = AHu[(m0 + g) * 33 + ks * 8 + tig + 4];
        Af[ks][3] = AHu[(m0 + g + 8) * 33 + ks * 8 + tig + 4];
    }

    // vtable passes 1+2: Ahi x Bhi, Ahi x Blo
#pragma unroll
    for (int nt = 0; nt < 16; nt++) {
        int colg = wn * 128 + nt * 8 + g;
        uint2 bh[4];
#pragma unroll
        for (int ks = 0; ks < 4; ks++)
            bh[ks] = __ldg(BH + ((ks * 256 + colg) * 4 + tig));
#pragma unroll
        for (int ks = 0; ks < 4; ks++)
            mma16816(c[nt][0], c[nt][1], c[nt][2], c[nt][3],
                     Af[ks][0], Af[ks][1], Af[ks][2], Af[ks][3], bh[ks].x, bh[ks].y);
#pragma unroll
        for (int ks = 0; ks < 4; ks++)
            bh[ks] = __ldg(BL + ((ks * 256 + colg) * 4 + tig));
#pragma unroll
        for (int ks = 0; ks < 4; ks++)
            mma16816(c[nt][0], c[nt][1], c[nt][2], c[nt][3],
                     Af[ks][0], Af[ks][1], Af[ks][2], Af[ks][3], bh[ks].x, bh[ks].y);
    }

    // vtable pass 3: Alo x Bhi
#pragma unroll
    for (int ks = 0; ks < 4; ks++) {
        Af[ks][0] = ALu[(m0 + g) * 33 + ks * 8 + tig];
        Af[ks][1] = ALu[(m0 + g + 8) * 33 + ks * 8 + tig];
        Af[ks][2] = ALu[(m0 + g) * 33 + ks * 8 + tig + 4];
        Af[ks][3] = ALu[(m0 + g + 8) * 33 + ks * 8 + tig + 4];
    }
#pragma unroll
    for (int nt = 0; nt < 16; nt++) {
        int colg = wn * 128 + nt * 8 + g;
        uint2 bh[4];
#pragma unroll
        for (int ks = 0; ks < 4; ks++)
            bh[ks] = __ldg(BH + ((ks * 256 + colg) * 4 + tig));
#pragma unroll
        for (int ks = 0; ks < 4; ks++)
            mma16816(c[nt][0], c[nt][1], c[nt][2], c[nt][3],
                     Af[ks][0], Af[ks][1], Af[ks][2], Af[ks][3], bh[ks].x, bh[ks].y);
    }

    // ---- logits GEMM: wn=0 -> t = x@Wt (+bt); wn=1 -> sl = src@Ws (+bs) ----
    {
        const unsigned* MHu = (wn == 0) ? XHu : AHu;
        const unsigned* MLu = (wn == 0) ? XLu : ALu;
        const uint2* LBH = (wn == 0) ? (const uint2*)g_WtHi : (const uint2*)g_WsHi;
        const uint2* LBL = (wn == 0) ? (const uint2*)g_WtLo : (const uint2*)g_WsLo;

        float cl0 = 0.f, cl1 = 0.f, cl2 = 0.f, cl3 = 0.f;
        unsigned Lf[4][4];
#pragma unroll
        for (int ks = 0; ks < 4; ks++) {
            Lf[ks][0] = MHu[(m0 + g) * 33 + ks * 8 + tig];
            Lf[ks][1] = MHu[(m0 + g + 8) * 33 + ks * 8 + tig];
            Lf[ks][2] = MHu[(m0 + g) * 33 + ks * 8 + tig + 4];
            Lf[ks][3] = MHu[(m0 + g + 8) * 33 + ks * 8 + tig + 4];
        }
#pragma unroll
        for (int ks = 0; ks < 4; ks++) {
            uint2 b = __ldg(LBH + (ks * 32 + g * 4 + tig));
            mma16816(cl0, cl1, cl2, cl3, Lf[ks][0], Lf[ks][1], Lf[ks][2], Lf[ks][3], b.x, b.y);
        }
#pragma unroll
        for (int ks = 0; ks < 4; ks++) {
            uint2 b = __ldg(LBL + (ks * 32 + g * 4 + tig));
            mma16816(cl0, cl1, cl2, cl3, Lf[ks][0], Lf[ks][1], Lf[ks][2], Lf[ks][3], b.x, b.y);
        }
#pragma unroll
        for (int ks = 0; ks < 4; ks++) {
            Lf[ks][0] = MLu[(m0 + g) * 33 + ks * 8 + tig];
            Lf[ks][1] = MLu[(m0 + g + 8) * 33 + ks * 8 + tig];
            Lf[ks][2] = MLu[(m0 + g) * 33 + ks * 8 + tig + 4];
            Lf[ks][3] = MLu[(m0 + g + 8) * 33 + ks * 8 + tig + 4];
        }
#pragma unroll
        for (int ks = 0; ks < 4; ks++) {
            uint2 b = __ldg(LBH + (ks * 32 + g * 4 + tig));
            mma16816(cl0, cl1, cl2, cl3, Lf[ks][0], Lf[ks][1], Lf[ks][2], Lf[ks][3], b.x, b.y);
        }

        if (tig < 2) {
            const float* bv = (wn == 0) ? bt : bs;
            float bias0 = __ldg(bv + 2 * tig);
            float bias1 = __ldg(bv + 2 * tig + 1);
            float* dst = (wn == 0) ? g_t : g_sl;
            int row0 = j0 + m0 + g, row1 = row0 + 8;
            if (row0 < N)
                *(float2*)(dst + row0 * 4 + 2 * tig) = make_float2(cl0 + bias0, cl1 + bias1);
            if (row1 < N)
                *(float2*)(dst + row1 * 4 + 2 * tig) = make_float2(cl2 + bias0, cl3 + bias1);
        }
    }
    __syncthreads();

    // ---- vtable epilogue: scale+bias, fp16 pack, stage to smem C [64][132] ----
#pragma unroll
    for (int nt = 0; nt < 16; nt++) {
        int col0 = wn * 128 + nt * 8 + 2 * tig;
        int s = col0 >> 6, o = col0 & 63, q = o >> 1;
        float bb0 = __ldg(b_lin + s * 64 + o) * 0.25f;
        float bb1 = __ldg(b_lin + s * 64 + o + 1) * 0.25f;
        __half2 h0 = __floats2half2_rn(c[nt][0] * 0.25f + bb0, c[nt][1] * 0.25f + bb1);
        __half2 h1 = __floats2half2_rn(c[nt][2] * 0.25f + bb0, c[nt][3] * 0.25f + bb1);
        CS[(m0 + g) * 132 + s * 32 + q]     = h0;
        CS[(m0 + g + 8) * 132 + s * 32 + q] = h1;
    }
    __syncthreads();

    const unsigned* cu = reinterpret_cast<const unsigned*>(CS);
    for (int it = t; it < 2048; it += 256) {
        int jloc = it >> 5, q = it & 31;
        int j = j0 + jloc;
        if (j < N) {
            uint4 u;
            u.x = cu[jloc * 132 + q];
            u.y = cu[jloc * 132 + 32 + q];
            u.z = cu[jloc * 132 + 64 + q];
            u.w = cu[jloc * 132 + 96 + q];
            ((uint4*)(g_vh + (size_t)j * 128))[q] = u;
        }
    }
}

// ---------------------------------------------------------------------------
// Inverted gather: one warp per source row j. v[j] loaded ONCE into registers;
// stream the referencing (n,k) pairs from the inverse index.
// ---------------------------------------------------------------------------
__global__ void __launch_bounds__(256) k_gather_inv(float* __restrict__ out, int N)
{
    int lane = threadIdx.x & 31;
    int j = (blockIdx.x * blockDim.x + threadIdx.x) >> 5;
    if (j >= N) return;

    int cnt = __ldg(&g_cnt[j]);
    if (cnt <= 0) return;
    if (cnt > DEGCAP) cnt = DEGCAP;

    float4 slv = __ldg((const float4*)g_sl + j);       // uniform

    // v row: one uint4 per lane = outputs (2*lane, 2*lane+1) for all 4 s
    uint4 u = __ldg((const uint4*)(g_vh + (size_t)j * 128) + lane);
    float2 f0 = __half22float2(*reinterpret_cast<__half2*>(&u.x));
    float2 f1 = __half22float2(*reinterpret_cast<__half2*>(&u.y));
    float2 f2 = __half22float2(*reinterpret_cast<__half2*>(&u.z));
    float2 f3 = __half22float2(*reinterpret_cast<__half2*>(&u.w));

    const int* lst = g_list + j * DEGCAP;

    for (int r0 = 0; r0 < cnt; r0 += 8) {
        int   myw = 0;
        float4 a4 = make_float4(0.f, 0.f, 0.f, 0.f);
        if (lane < 8) {
            int i = r0 + lane;
            if (i < cnt) {
                myw = __ldg(lst + i);
                int n = myw >> 4;                       // K = 16
                float4 tv = __ldg((const float4*)g_t + n);
                float l0 = tv.x + slv.x, l1 = tv.y + slv.y;
                float l2 = tv.z + slv.z, l3 = tv.w + slv.w;
                float m = fmaxf(fmaxf(l0, l1), fmaxf(l2, l3));
                float e0 = __expf(l0 - m), e1 = __expf(l1 - m);
                float e2 = __expf(l2 - m), e3 = __expf(l3 - m);
                float inv = 1.0f / (e0 + e1 + e2 + e3);
                a4 = make_float4(e0 * inv, e1 * inv, e2 * inv, e3 * inv);
            }
        }
        int lim = cnt - r0; if (lim > 8) lim = 8;
#pragma unroll
        for (int p = 0; p < 8; p++) {
            if (p >= lim) break;
            int   w  = __shfl_sync(0xFFFFFFFFu, myw,  p);
            float a0 = __shfl_sync(0xFFFFFFFFu, a4.x, p);
            float a1 = __shfl_sync(0xFFFFFFFFu, a4.y, p);
            float a2 = __shfl_sync(0xFFFFFFFFu, a4.z, p);
            float a3 = __shfl_sync(0xFFFFFFFFu, a4.w, p);
            float2 r;
            r.x = a0 * f0.x + a1 * f1.x + a2 * f2.x + a3 * f3.x;
            r.y = a0 * f0.y + a1 * f1.y + a2 * f2.y + a3 * f3.y;
            __stcs((float2*)out + (size_t)w * 32 + lane, r);
        }
    }
}

// ---------------------------------------------------------------------------
extern "C" void kernel_launch(void* const* d_in, const int* in_sizes, int n_in,
                              void* d_out, int out_size)
{
    const float* x     = (const float*)d_in[0];
    const float* src   = (const float*)d_in[1];
    const int*   nidx  = (const int*)d_in[2];
    const float* Wt    = (const float*)d_in[3];
    const float* bt    = (const float*)d_in[4];
    const float* Ws    = (const float*)d_in[5];
    const float* bs    = (const float*)d_in[6];
    const float* W_lin = (const float*)d_in[7];
    const float* b_lin = (const float*)d_in[8];
    float* out = (float*)d_out;

    int N  = in_sizes[0] / CDIM;       // 50000
    int NK = in_sizes[2];              // N*K = 800000
    if (N > MAXN) N = MAXN;

    int tiles = (N + 63) / 64;         // 782
    int buildBlocks = (NK + 255) / 256;

    // 0) fragment prep + zero inverse-index counts
    k_prep<<<34 + (MAXN + 255) / 256, 256>>>(W_lin, Wt, Ws);

    // 1) fused v-table + logits (tensor pipe) + inverse-index build
    k_tables<<<tiles + buildBlocks, 256>>>(x, src, bt, bs, b_lin, nidx, N, NK, tiles);

    // 2) inverted gather: one warp per source row
    k_gather_inv<<<(N + 7) / 8, 256>>>(out, N);
}

// round 12
// speedup vs baseline: 1.1819x; 1.1819x over previous
#include <cuda_runtime.h>
#include <cuda_fp16.h>

// Problem constants (fixed by dataset)
#define MAXN 50000
#define CDIM 64
#define SDIM 4
#define ODIM 64
#define KNEI 16

// Scratch (static __device__ — allocation-free per harness rules)
__device__ __half2 g_vh[MAXN * 128];          // 25.6 MB v-table (fp16)
__device__ float   g_t[MAXN * SDIM];          // x[n]@Wt + bt
__device__ float   g_sl[MAXN * SDIM];         // src[j]@Ws + bs

// W_lin pre-split into mma B-fragment layout (fp16 hi; lo kept only for logits W).
__device__ __half2 g_Bhi[8192];
__device__ __half2 g_WtHi[256];
__device__ __half2 g_WtLo[256];
__device__ __half2 g_WsHi[256];
__device__ __half2 g_WsLo[256];

// ---------------------------------------------------------------------------
// Prep: split W_lin (+ Wt, Ws) into fp16 B-fragments.
// ---------------------------------------------------------------------------
__global__ void k_prep(const float* __restrict__ W_lin,
                       const float* __restrict__ Wt,
                       const float* __restrict__ Ws)
{
    int i = blockIdx.x * 256 + threadIdx.x;
    if (i < 8192) {
        int wh  = i & 1;
        int tig = (i >> 1) & 3;
        int col = (i >> 3) & 255;
        int ks  = i >> 11;
        int s = col >> 6, o = col & 63;
        int k = ks * 16 + wh * 8 + 2 * tig;

        float w0 = __ldg(W_lin + s * 4096 + k * 64 + o);
        float w1 = __ldg(W_lin + s * 4096 + (k + 1) * 64 + o);
        g_Bhi[i] = __halves2half2(__float2half_rn(w0), __float2half_rn(w1));
    } else if (i < 8704) {
        int idx = i - 8192;
        int mat = idx >> 8;            // 0 = Wt, 1 = Ws
        int e   = idx & 255;
        int wh = e & 1, tig = (e >> 1) & 3, col = (e >> 3) & 7, ks = (e >> 6) & 3;
        int k = ks * 16 + wh * 8 + 2 * tig;
        const float* W = mat ? Ws : Wt;
        float w0 = 0.f, w1 = 0.f;
        if (col < 4) {
            w0 = __ldg(W + k * 4 + col);
            w1 = __ldg(W + (k + 1) * 4 + col);
        }
        __half h0 = __float2half_rn(w0), h1 = __float2half_rn(w1);
        __half l0 = __float2half_rn(w0 - __half2float(h0));
        __half l1 = __float2half_rn(w1 - __half2float(h1));
        if (mat) { g_WsHi[e] = __halves2half2(h0, h1); g_WsLo[e] = __halves2half2(l0, l1); }
        else     { g_WtHi[e] = __halves2half2(h0, h1); g_WtLo[e] = __halves2half2(l0, l1); }
    }
}

__device__ __forceinline__ void mma16816(float& c0, float& c1, float& c2, float& c3,
                                         unsigned a0, unsigned a1, unsigned a2, unsigned a3,
                                         unsigned b0, unsigned b1)
{
    asm volatile("mma.sync.aligned.m16n8k16.row.col.f32.f16.f16.f32 "
                 "{%0,%1,%2,%3}, {%4,%5,%6,%7}, {%8,%9}, {%0,%1,%2,%3};"
                 : "+f"(c0), "+f"(c1), "+f"(c2), "+f"(c3)
                 : "r"(a0), "r"(a1), "r"(a2), "r"(a3), "r"(b0), "r"(b1));
}

// ---------------------------------------------------------------------------
// Fused kernel: 64 rows/block — v-table GEMM (single-pass fp16 HMMA) + both
// logits GEMMs (3-pass hi/lo for ~fp32 accuracy).
// ---------------------------------------------------------------------------
__global__ void __launch_bounds__(256, 2) k_tables(const float* __restrict__ x,
                                                   const float* __restrict__ src,
                                                   const float* __restrict__ bt,
                                                   const float* __restrict__ bs,
                                                   const float* __restrict__ b_lin,
                                                   int N)
{
    __shared__ __align__(16) char smraw[33856];
    __half2* AH = reinterpret_cast<__half2*>(smraw);            // src hi [64][33]
    __half2* AL = AH + 2112;                                    // src lo
    __half2* XH = AH + 4224;                                    // x hi
    __half2* XL = AH + 6336;                                    // x lo
    __half2* CS = reinterpret_cast<__half2*>(smraw);            // epilogue reuse [64][132]

    int t    = threadIdx.x;
    int lane = t & 31;
    int wid  = t >> 5;
    int g    = lane >> 2;
    int tig  = lane & 3;
    int wm   = wid & 3;
    int wn   = wid >> 2;
    int m0   = wm * 16;
    int j0   = blockIdx.x * 64;

    // ---- stage src and x tiles as fp16 hi/lo ----
    {
        int row  = t >> 2;
        int quad = t & 3;
        int jg = j0 + row;
        const float4* srp = (const float4*)(src + (size_t)jg * CDIM) + quad * 4;
        const float4* xrp = (const float4*)(x   + (size_t)jg * CDIM) + quad * 4;
#pragma unroll
        for (int ii = 0; ii < 4; ii++) {
            float4 v = (jg < N) ? __ldg(srp + ii) : make_float4(0.f, 0.f, 0.f, 0.f);
            float4 u = (jg < N) ? __ldg(xrp + ii) : make_float4(0.f, 0.f, 0.f, 0.f);
            int cp = quad * 8 + ii * 2;
            {
                __half hx = __float2half_rn(v.x), hy = __float2half_rn(v.y);
                __half hz = __float2half_rn(v.z), hw = __float2half_rn(v.w);
                AH[row * 33 + cp]     = __halves2half2(hx, hy);
                AH[row * 33 + cp + 1] = __halves2half2(hz, hw);
                AL[row * 33 + cp]     = __halves2half2(__float2half_rn(v.x - __half2float(hx)),
                                                       __float2half_rn(v.y - __half2float(hy)));
                AL[row * 33 + cp + 1] = __halves2half2(__float2half_rn(v.z - __half2float(hz)),
                                                       __float2half_rn(v.w - __half2float(hw)));
            }
            {
                __half hx = __float2half_rn(u.x), hy = __float2half_rn(u.y);
                __half hz = __float2half_rn(u.z), hw = __float2half_rn(u.w);
                XH[row * 33 + cp]     = __halves2half2(hx, hy);
                XH[row * 33 + cp + 1] = __halves2half2(hz, hw);
                XL[row * 33 + cp]     = __halves2half2(__float2half_rn(u.x - __half2float(hx)),
                                                       __float2half_rn(u.y - __half2float(hy)));
                XL[row * 33 + cp + 1] = __halves2half2(__float2half_rn(u.z - __half2float(hz)),
                                                       __float2half_rn(u.w - __half2float(hw)));
            }
        }
    }
    __syncthreads();

    const unsigned* AHu = reinterpret_cast<const unsigned*>(AH);
    const unsigned* ALu = reinterpret_cast<const unsigned*>(AL);
    const unsigned* XHu = reinterpret_cast<const unsigned*>(XH);
    const unsigned* XLu = reinterpret_cast<const unsigned*>(XL);
    const uint2* BH = reinterpret_cast<const uint2*>(g_Bhi);

    float c[16][4];
#pragma unroll
    for (int nt = 0; nt < 16; nt++)
#pragma unroll
        for (int r = 0; r < 4; r++) c[nt][r] = 0.f;

    unsigned Af[4][4];
#pragma unroll
    for (int ks = 0; ks < 4; ks++) {
        Af[ks][0] = AHu[(m0 + g) * 33 + ks * 8 + tig];
        Af[ks][1] = AHu[(m0 + g + 8) * 33 + ks * 8 + tig];
        Af[ks][2] = AHu[(m0 + g) * 33 + ks * 8 + tig + 4];
        Af[ks][3] = AHu[(m0 + g + 8) * 33 + ks * 8 + tig + 4];
    }

    // vtable: single pass Ahi x Bhi (v is stored fp16 anyway)
#pragma unroll
    for (int nt = 0; nt < 16; nt++) {
        int colg = wn * 128 + nt * 8 + g;
        uint2 bh[4];
#pragma unroll
        for (int ks = 0; ks < 4; ks++)
            bh[ks] = __ldg(BH + ((ks * 256 + colg) * 4 + tig));
#pragma unroll
        for (int ks = 0; ks < 4; ks++)
            mma16816(c[nt][0], c[nt][1], c[nt][2], c[nt][3],
                     Af[ks][0], Af[ks][1], Af[ks][2], Af[ks][3], bh[ks].x, bh[ks].y);
    }

    // ---- logits GEMM (3-pass hi/lo): wn=0 -> t = x@Wt+bt; wn=1 -> sl = src@Ws+bs
    {
        const unsigned* MHu = (wn == 0) ? XHu : AHu;
        const unsigned* MLu = (wn == 0) ? XLu : ALu;
        const uint2* LBH = (wn == 0) ? (const uint2*)g_WtHi : (const uint2*)g_WsHi;
        const uint2* LBL = (wn == 0) ? (const uint2*)g_WtLo : (const uint2*)g_WsLo;

        float cl0 = 0.f, cl1 = 0.f, cl2 = 0.f, cl3 = 0.f;
        unsigned Lf[4][4];
#pragma unroll
        for (int ks = 0; ks < 4; ks++) {
            Lf[ks][0] = MHu[(m0 + g) * 33 + ks * 8 + tig];
            Lf[ks][1] = MHu[(m0 + g + 8) * 33 + ks * 8 + tig];
            Lf[ks][2] = MHu[(m0 + g) * 33 + ks * 8 + tig + 4];
            Lf[ks][3] = MHu[(m0 + g + 8) * 33 + ks * 8 + tig + 4];
        }
#pragma unroll
        for (int ks = 0; ks < 4; ks++) {
            uint2 b = __ldg(LBH + (ks * 32 + g * 4 + tig));
            mma16816(cl0, cl1, cl2, cl3, Lf[ks][0], Lf[ks][1], Lf[ks][2], Lf[ks][3], b.x, b.y);
        }
#pragma unroll
        for (int ks = 0; ks < 4; ks++) {
            uint2 b = __ldg(LBL + (ks * 32 + g * 4 + tig));
            mma16816(cl0, cl1, cl2, cl3, Lf[ks][0], Lf[ks][1], Lf[ks][2], Lf[ks][3], b.x, b.y);
        }
#pragma unroll
        for (int ks = 0; ks < 4; ks++) {
            Lf[ks][0] = MLu[(m0 + g) * 33 + ks * 8 + tig];
            Lf[ks][1] = MLu[(m0 + g + 8) * 33 + ks * 8 + tig];
            Lf[ks][2] = MLu[(m0 + g) * 33 + ks * 8 + tig + 4];
            Lf[ks][3] = MLu[(m0 + g + 8) * 33 + ks * 8 + tig + 4];
        }
#pragma unroll
        for (int ks = 0; ks < 4; ks++) {
            uint2 b = __ldg(LBH + (ks * 32 + g * 4 + tig));
            mma16816(cl0, cl1, cl2, cl3, Lf[ks][0], Lf[ks][1], Lf[ks][2], Lf[ks][3], b.x, b.y);
        }

        if (tig < 2) {
            const float* bv = (wn == 0) ? bt : bs;
            float bias0 = __ldg(bv + 2 * tig);
            float bias1 = __ldg(bv + 2 * tig + 1);
            float* dst = (wn == 0) ? g_t : g_sl;
            int row0 = j0 + m0 + g, row1 = row0 + 8;
            if (row0 < N)
                *(float2*)(dst + row0 * 4 + 2 * tig) = make_float2(cl0 + bias0, cl1 + bias1);
            if (row1 < N)
                *(float2*)(dst + row1 * 4 + 2 * tig) = make_float2(cl2 + bias0, cl3 + bias1);
        }
    }
    __syncthreads();

    // ---- vtable epilogue: scale+bias, fp16 pack, stage to smem C [64][132] ----
#pragma unroll
    for (int nt = 0; nt < 16; nt++) {
        int col0 = wn * 128 + nt * 8 + 2 * tig;
        int s = col0 >> 6, o = col0 & 63, q = o >> 1;
        float bb0 = __ldg(b_lin + s * 64 + o) * 0.25f;
        float bb1 = __ldg(b_lin + s * 64 + o + 1) * 0.25f;
        __half2 h0 = __floats2half2_rn(c[nt][0] * 0.25f + bb0, c[nt][1] * 0.25f + bb1);
        __half2 h1 = __floats2half2_rn(c[nt][2] * 0.25f + bb0, c[nt][3] * 0.25f + bb1);
        CS[(m0 + g) * 132 + s * 32 + q]     = h0;
        CS[(m0 + g + 8) * 132 + s * 32 + q] = h1;
    }
    __syncthreads();

    const unsigned* cu = reinterpret_cast<const unsigned*>(CS);
    for (int it = t; it < 2048; it += 256) {
        int jloc = it >> 5, q = it & 31;
        int j = j0 + jloc;
        if (j < N) {
            uint4 u;
            u.x = cu[jloc * 132 + q];
            u.y = cu[jloc * 132 + 32 + q];
            u.z = cu[jloc * 132 + 64 + q];
            u.w = cu[jloc * 132 + 96 + q];
            ((uint4*)(g_vh + (size_t)j * 128))[q] = u;
        }
    }
}

// ---------------------------------------------------------------------------
// Fused softmax + gather + combine, 8 pairs per warp (forward; R10 version).
// ---------------------------------------------------------------------------
__global__ void __launch_bounds__(256) k_gather(const int* __restrict__ idx,
                                                float* __restrict__ out,
                                                int total /* N*K */)
{
    int lane = threadIdx.x & 31;
    int gw   = (blockIdx.x * blockDim.x + threadIdx.x) >> 5;
    int w    = gw * 8;
    if (w >= total) return;

    int n = w >> 4;
    float4 tv = __ldg((const float4*)g_t + n);

    int   myj = 0;
    float4 a4 = make_float4(0.f, 0.f, 0.f, 0.f);
    if (lane < 8) {
        int wi = w + lane;
        if (wi < total) {
            myj = __ldg(idx + wi);
            float4 sv = __ldg((const float4*)g_sl + myj);
            float l0 = tv.x + sv.x, l1 = tv.y + sv.y;
            float l2 = tv.z + sv.z, l3 = tv.w + sv.w;
            float m = fmaxf(fmaxf(l0, l1), fmaxf(l2, l3));
            float e0 = __expf(l0 - m), e1 = __expf(l1 - m);
            float e2 = __expf(l2 - m), e3 = __expf(l3 - m);
            float inv = 1.0f / (e0 + e1 + e2 + e3);
            a4 = make_float4(e0 * inv, e1 * inv, e2 * inv, e3 * inv);
        }
    }

    if (w + 7 < total) {
        float2* ob = (float2*)out + (size_t)w * 32 + lane;
#pragma unroll
        for (int p = 0; p < 8; p++) {
            int   j  = __shfl_sync(0xFFFFFFFFu, myj,  p);
            float a0 = __shfl_sync(0xFFFFFFFFu, a4.x, p);
            float a1 = __shfl_sync(0xFFFFFFFFu, a4.y, p);
            float a2 = __shfl_sync(0xFFFFFFFFu, a4.z, p);
            float a3 = __shfl_sync(0xFFFFFFFFu, a4.w, p);

            uint4 u = __ldg((const uint4*)(g_vh + (size_t)j * 128) + lane);
            float2 f0 = __half22float2(*reinterpret_cast<__half2*>(&u.x));
            float2 f1 = __half22float2(*reinterpret_cast<__half2*>(&u.y));
            float2 f2 = __half22float2(*reinterpret_cast<__half2*>(&u.z));
            float2 f3 = __half22float2(*reinterpret_cast<__half2*>(&u.w));
            float2 r;
            r.x = a0 * f0.x + a1 * f1.x + a2 * f2.x + a3 * f3.x;
            r.y = a0 * f0.y + a1 * f1.y + a2 * f2.y + a3 * f3.y;
            __stcs(ob + p * 32, r);
        }
    } else {
        for (int p = 0; p < 8 && w + p < total; p++) {
            int   j  = __shfl_sync(0xFFFFFFFFu, myj,  p);
            float a0 = __shfl_sync(0xFFFFFFFFu, a4.x, p);
            float a1 = __shfl_sync(0xFFFFFFFFu, a4.y, p);
            float a2 = __shfl_sync(0xFFFFFFFFu, a4.z, p);
            float a3 = __shfl_sync(0xFFFFFFFFu, a4.w, p);

            uint4 u = __ldg((const uint4*)(g_vh + (size_t)j * 128) + lane);
            float2 f0 = __half22float2(*reinterpret_cast<__half2*>(&u.x));
            float2 f1 = __half22float2(*reinterpret_cast<__half2*>(&u.y));
            float2 f2 = __half22float2(*reinterpret_cast<__half2*>(&u.z));
            float2 f3 = __half22float2(*reinterpret_cast<__half2*>(&u.w));
            float2 r;
            r.x = a0 * f0.x + a1 * f1.x + a2 * f2.x + a3 * f3.x;
            r.y = a0 * f0.y + a1 * f1.y + a2 * f2.y + a3 * f3.y;
            __stcs((float2*)out + (size_t)(w + p) * 32 + lane, r);
        }
    }
}

// ---------------------------------------------------------------------------
extern "C" void kernel_launch(void* const* d_in, const int* in_sizes, int n_in,
                              void* d_out, int out_size)
{
    const float* x     = (const float*)d_in[0];
    const float* src   = (const float*)d_in[1];
    const int*   nidx  = (const int*)d_in[2];
    const float* Wt    = (const float*)d_in[3];
    const float* bt    = (const float*)d_in[4];
    const float* Ws    = (const float*)d_in[5];
    const float* bs    = (const float*)d_in[6];
    const float* W_lin = (const float*)d_in[7];
    const float* b_lin = (const float*)d_in[8];
    float* out = (float*)d_out;

    int N  = in_sizes[0] / CDIM;       // 50000
    int NK = in_sizes[2];              // N*K = 800000
    if (N > MAXN) N = MAXN;

    int tiles = (N + 63) / 64;         // 782

    // 0) fragment prep
    k_prep<<<34, 256>>>(W_lin, Wt, Ws);

    // 1) fused v-table (single-pass fp16 HMMA) + logits (hi/lo HMMA)
    k_tables<<<tiles, 256>>>(x, src, bt, bs, b_lin, N);

    // 2) fused softmax + gather + combine: 8 pairs per warp
    int gwarps = (NK + 7) / 8;
    k_gather<<<(gwarps + 7) / 8, 256>>>(nidx, out, NK);
}

// round 13
// speedup vs baseline: 1.2225x; 1.0344x over previous
#include <cuda_runtime.h>
#include <cuda_fp16.h>

// Problem constants (fixed by dataset)
#define MAXN 50000
#define CDIM 64
#define SDIM 4
#define ODIM 64
#define KNEI 16

// Scratch (static __device__ — allocation-free per harness rules)
__device__ __half2 g_vh[MAXN * 128];          // 25.6 MB v-table (fp16)
__device__ float   g_t[MAXN * SDIM];          // x[n]@Wt + bt
__device__ float   g_sl[MAXN * SDIM];         // src[j]@Ws + bs

// W_lin / Wt / Ws pre-split into mma B-fragment layout (fp16).
__device__ __half2 g_Bhi[8192];
__device__ __half2 g_WtHi[256];
__device__ __half2 g_WsHi[256];

// ---------------------------------------------------------------------------
// Prep: split W_lin (+ Wt, Ws) into fp16 B-fragments.
// ---------------------------------------------------------------------------
__global__ void k_prep(const float* __restrict__ W_lin,
                       const float* __restrict__ Wt,
                       const float* __restrict__ Ws)
{
    int i = blockIdx.x * 256 + threadIdx.x;
    if (i < 8192) {
        int wh  = i & 1;
        int tig = (i >> 1) & 3;
        int col = (i >> 3) & 255;
        int ks  = i >> 11;
        int s = col >> 6, o = col & 63;
        int k = ks * 16 + wh * 8 + 2 * tig;

        float w0 = __ldg(W_lin + s * 4096 + k * 64 + o);
        float w1 = __ldg(W_lin + s * 4096 + (k + 1) * 64 + o);
        g_Bhi[i] = __halves2half2(__float2half_rn(w0), __float2half_rn(w1));
    } else if (i < 8704) {
        int idx = i - 8192;
        int mat = idx >> 8;            // 0 = Wt, 1 = Ws
        int e   = idx & 255;
        int wh = e & 1, tig = (e >> 1) & 3, col = (e >> 3) & 7, ks = (e >> 6) & 3;
        int k = ks * 16 + wh * 8 + 2 * tig;
        const float* W = mat ? Ws : Wt;
        float w0 = 0.f, w1 = 0.f;
        if (col < 4) {
            w0 = __ldg(W + k * 4 + col);
            w1 = __ldg(W + (k + 1) * 4 + col);
        }
        __half2 h = __halves2half2(__float2half_rn(w0), __float2half_rn(w1));
        if (mat) g_WsHi[e] = h;
        else     g_WtHi[e] = h;
    }
}

__device__ __forceinline__ void mma16816(float& c0, float& c1, float& c2, float& c3,
                                         unsigned a0, unsigned a1, unsigned a2, unsigned a3,
                                         unsigned b0, unsigned b1)
{
    asm volatile("mma.sync.aligned.m16n8k16.row.col.f32.f16.f16.f32 "
                 "{%0,%1,%2,%3}, {%4,%5,%6,%7}, {%8,%9}, {%0,%1,%2,%3};"
                 : "+f"(c0), "+f"(c1), "+f"(c2), "+f"(c3)
                 : "r"(a0), "r"(a1), "r"(a2), "r"(a3), "r"(b0), "r"(b1));
}

// ---------------------------------------------------------------------------
// Fused kernel: 64 rows/block — v-table GEMM + both logits GEMMs, all
// single-pass fp16 HMMA.
// ---------------------------------------------------------------------------
__global__ void __launch_bounds__(256, 2) k_tables(const float* __restrict__ x,
                                                   const float* __restrict__ src,
                                                   const float* __restrict__ bt,
                                                   const float* __restrict__ bs,
                                                   const float* __restrict__ b_lin,
                                                   int N)
{
    __shared__ __align__(16) char smraw[33856];
    __half2* AH = reinterpret_cast<__half2*>(smraw);            // src fp16 [64][33]
    __half2* XH = AH + 2112;                                    // x   fp16 [64][33]
    __half2* CS = reinterpret_cast<__half2*>(smraw);            // epilogue reuse [64][132]

    int t    = threadIdx.x;
    int lane = t & 31;
    int wid  = t >> 5;
    int g    = lane >> 2;
    int tig  = lane & 3;
    int wm   = wid & 3;
    int wn   = wid >> 2;
    int m0   = wm * 16;
    int j0   = blockIdx.x * 64;

    // ---- stage src and x tiles as fp16 ----
    {
        int row  = t >> 2;
        int quad = t & 3;
        int jg = j0 + row;
        const float4* srp = (const float4*)(src + (size_t)jg * CDIM) + quad * 4;
        const float4* xrp = (const float4*)(x   + (size_t)jg * CDIM) + quad * 4;
#pragma unroll
        for (int ii = 0; ii < 4; ii++) {
            float4 v = (jg < N) ? __ldg(srp + ii) : make_float4(0.f, 0.f, 0.f, 0.f);
            float4 u = (jg < N) ? __ldg(xrp + ii) : make_float4(0.f, 0.f, 0.f, 0.f);
            int cp = quad * 8 + ii * 2;
            AH[row * 33 + cp]     = __floats2half2_rn(v.x, v.y);
            AH[row * 33 + cp + 1] = __floats2half2_rn(v.z, v.w);
            XH[row * 33 + cp]     = __floats2half2_rn(u.x, u.y);
            XH[row * 33 + cp + 1] = __floats2half2_rn(u.z, u.w);
        }
    }
    __syncthreads();

    const unsigned* AHu = reinterpret_cast<const unsigned*>(AH);
    const unsigned* XHu = reinterpret_cast<const unsigned*>(XH);
    const uint2* BH = reinterpret_cast<const uint2*>(g_Bhi);

    float c[16][4];
#pragma unroll
    for (int nt = 0; nt < 16; nt++)
#pragma unroll
        for (int r = 0; r < 4; r++) c[nt][r] = 0.f;

    unsigned Af[4][4];
#pragma unroll
    for (int ks = 0; ks < 4; ks++) {
        Af[ks][0] = AHu[(m0 + g) * 33 + ks * 8 + tig];
        Af[ks][1] = AHu[(m0 + g + 8) * 33 + ks * 8 + tig];
        Af[ks][2] = AHu[(m0 + g) * 33 + ks * 8 + tig + 4];
        Af[ks][3] = AHu[(m0 + g + 8) * 33 + ks * 8 + tig + 4];
    }

    // vtable: single pass (v is stored fp16 anyway)
#pragma unroll
    for (int nt = 0; nt < 16; nt++) {
        int colg = wn * 128 + nt * 8 + g;
        uint2 bh[4];
#pragma unroll
        for (int ks = 0; ks < 4; ks++)
            bh[ks] = __ldg(BH + ((ks * 256 + colg) * 4 + tig));
#pragma unroll
        for (int ks = 0; ks < 4; ks++)
            mma16816(c[nt][0], c[nt][1], c[nt][2], c[nt][3],
                     Af[ks][0], Af[ks][1], Af[ks][2], Af[ks][3], bh[ks].x, bh[ks].y);
    }

    // ---- logits GEMM (single-pass fp16): wn=0 -> t = x@Wt+bt; wn=1 -> sl = src@Ws+bs
    {
        const unsigned* MHu = (wn == 0) ? XHu : AHu;
        const uint2* LBH = (wn == 0) ? (const uint2*)g_WtHi : (const uint2*)g_WsHi;

        float cl0 = 0.f, cl1 = 0.f, cl2 = 0.f, cl3 = 0.f;
#pragma unroll
        for (int ks = 0; ks < 4; ks++) {
            unsigned L0 = MHu[(m0 + g) * 33 + ks * 8 + tig];
            unsigned L1 = MHu[(m0 + g + 8) * 33 + ks * 8 + tig];
            unsigned L2 = MHu[(m0 + g) * 33 + ks * 8 + tig + 4];
            unsigned L3 = MHu[(m0 + g + 8) * 33 + ks * 8 + tig + 4];
            uint2 b = __ldg(LBH + (ks * 32 + g * 4 + tig));
            mma16816(cl0, cl1, cl2, cl3, L0, L1, L2, L3, b.x, b.y);
        }

        if (tig < 2) {
            const float* bv = (wn == 0) ? bt : bs;
            float bias0 = __ldg(bv + 2 * tig);
            float bias1 = __ldg(bv + 2 * tig + 1);
            float* dst = (wn == 0) ? g_t : g_sl;
            int row0 = j0 + m0 + g, row1 = row0 + 8;
            if (row0 < N)
                *(float2*)(dst + row0 * 4 + 2 * tig) = make_float2(cl0 + bias0, cl1 + bias1);
            if (row1 < N)
                *(float2*)(dst + row1 * 4 + 2 * tig) = make_float2(cl2 + bias0, cl3 + bias1);
        }
    }
    __syncthreads();

    // ---- vtable epilogue: scale+bias, fp16 pack, stage to smem C [64][132] ----
#pragma unroll
    for (int nt = 0; nt < 16; nt++) {
        int col0 = wn * 128 + nt * 8 + 2 * tig;
        int s = col0 >> 6, o = col0 & 63, q = o >> 1;
        float bb0 = __ldg(b_lin + s * 64 + o) * 0.25f;
        float bb1 = __ldg(b_lin + s * 64 + o + 1) * 0.25f;
        __half2 h0 = __floats2half2_rn(c[nt][0] * 0.25f + bb0, c[nt][1] * 0.25f + bb1);
        __half2 h1 = __floats2half2_rn(c[nt][2] * 0.25f + bb0, c[nt][3] * 0.25f + bb1);
        CS[(m0 + g) * 132 + s * 32 + q]     = h0;
        CS[(m0 + g + 8) * 132 + s * 32 + q] = h1;
    }
    __syncthreads();

    const unsigned* cu = reinterpret_cast<const unsigned*>(CS);
    for (int it = t; it < 2048; it += 256) {
        int jloc = it >> 5, q = it & 31;
        int j = j0 + jloc;
        if (j < N) {
            uint4 u;
            u.x = cu[jloc * 132 + q];
            u.y = cu[jloc * 132 + 32 + q];
            u.z = cu[jloc * 132 + 64 + q];
            u.w = cu[jloc * 132 + 96 + q];
            ((uint4*)(g_vh + (size_t)j * 128))[q] = u;
        }
    }
}

// ---------------------------------------------------------------------------
// Fused softmax + gather + combine, 8 pairs per warp.
// ---------------------------------------------------------------------------
__global__ void __launch_bounds__(256) k_gather(const int* __restrict__ idx,
                                                float* __restrict__ out,
                                                int total /* N*K */)
{
    int lane = threadIdx.x & 31;
    int gw   = (blockIdx.x * blockDim.x + threadIdx.x) >> 5;
    int w    = gw * 8;
    if (w >= total) return;

    int n = w >> 4;
    float4 tv = __ldg((const float4*)g_t + n);

    int   myj = 0;
    float4 a4 = make_float4(0.f, 0.f, 0.f, 0.f);
    if (lane < 8) {
        int wi = w + lane;
        if (wi < total) {
            myj = __ldg(idx + wi);
            float4 sv = __ldg((const float4*)g_sl + myj);
            float l0 = tv.x + sv.x, l1 = tv.y + sv.y;
            float l2 = tv.z + sv.z, l3 = tv.w + sv.w;
            float m = fmaxf(fmaxf(l0, l1), fmaxf(l2, l3));
            float e0 = __expf(l0 - m), e1 = __expf(l1 - m);
            float e2 = __expf(l2 - m), e3 = __expf(l3 - m);
            float inv = 1.0f / (e0 + e1 + e2 + e3);
            a4 = make_float4(e0 * inv, e1 * inv, e2 * inv, e3 * inv);
        }
    }

    if (w + 7 < total) {
        float2* ob = (float2*)out + (size_t)w * 32 + lane;
#pragma unroll
        for (int p = 0; p < 8; p++) {
            int   j  = __shfl_sync(0xFFFFFFFFu, myj,  p);
            float a0 = __shfl_sync(0xFFFFFFFFu, a4.x, p);
            float a1 = __shfl_sync(0xFFFFFFFFu, a4.y, p);
            float a2 = __shfl_sync(0xFFFFFFFFu, a4.z, p);
            float a3 = __shfl_sync(0xFFFFFFFFu, a4.w, p);

            uint4 u = __ldg((const uint4*)(g_vh + (size_t)j * 128) + lane);
            float2 f0 = __half22float2(*reinterpret_cast<__half2*>(&u.x));
            float2 f1 = __half22float2(*reinterpret_cast<__half2*>(&u.y));
            float2 f2 = __half22float2(*reinterpret_cast<__half2*>(&u.z));
            float2 f3 = __half22float2(*reinterpret_cast<__half2*>(&u.w));
            float2 r;
            r.x = a0 * f0.x + a1 * f1.x + a2 * f2.x + a3 * f3.x;
            r.y = a0 * f0.y + a1 * f1.y + a2 * f2.y + a3 * f3.y;
            __stcs(ob + p * 32, r);
        }
    } else {
        for (int p = 0; p < 8 && w + p < total; p++) {
            int   j  = __shfl_sync(0xFFFFFFFFu, myj,  p);
            float a0 = __shfl_sync(0xFFFFFFFFu, a4.x, p);
            float a1 = __shfl_sync(0xFFFFFFFFu, a4.y, p);
            float a2 = __shfl_sync(0xFFFFFFFFu, a4.z, p);
            float a3 = __shfl_sync(0xFFFFFFFFu, a4.w, p);

            uint4 u = __ldg((const uint4*)(g_vh + (size_t)j * 128) + lane);
            float2 f0 = __half22float2(*reinterpret_cast<__half2*>(&u.x));
            float2 f1 = __half22float2(*reinterpret_cast<__half2*>(&u.y));
            float2 f2 = __half22float2(*reinterpret_cast<__half2*>(&u.z));
            float2 f3 = __half22float2(*reinterpret_cast<__half2*>(&u.w));
            float2 r;
            r.x = a0 * f0.x + a1 * f1.x + a2 * f2.x + a3 * f3.x;
            r.y = a0 * f0.y + a1 * f1.y + a2 * f2.y + a3 * f3.y;
            __stcs((float2*)out + (size_t)(w + p) * 32 + lane, r);
        }
    }
}

// ---------------------------------------------------------------------------
extern "C" void kernel_launch(void* const* d_in, const int* in_sizes, int n_in,
                              void* d_out, int out_size)
{
    const float* x     = (const float*)d_in[0];
    const float* src   = (const float*)d_in[1];
    const int*   nidx  = (const int*)d_in[2];
    const float* Wt    = (const float*)d_in[3];
    const float* bt    = (const float*)d_in[4];
    const float* Ws    = (const float*)d_in[5];
    const float* bs    = (const float*)d_in[6];
    const float* W_lin = (const float*)d_in[7];
    const float* b_lin = (const float*)d_in[8];
    float* out = (float*)d_out;

    int N  = in_sizes[0] / CDIM;       // 50000
    int NK = in_sizes[2];              // N*K = 800000
    if (N > MAXN) N = MAXN;

    int tiles = (N + 63) / 64;         // 782

    // 0) fragment prep
    k_prep<<<34, 256>>>(W_lin, Wt, Ws);

    // 1) fused v-table + logits (single-pass fp16 HMMA)
    k_tables<<<tiles, 256>>>(x, src, bt, bs, b_lin, N);

    // 2) fused softmax + gather + combine: 8 pairs per warp
    int gwarps = (NK + 7) / 8;
    k_gather<<<(gwarps + 7) / 8, 256>>>(nidx, out, NK);
}